// round 7
// baseline (speedup 1.0000x reference)
#include <cuda_runtime.h>
#include <cuda_fp16.h>
#include <math.h>
#include <stdint.h>
#include <stddef.h>

// ---------------- problem constants ----------------
#define BB    8192
#define TT    9
#define INPC  81
#define HH    512

#define KCONV 736        // 729 padded (mult of 32)
#define NCONV 3840       // 3645 padded (mult of 128)
#define FPAD  416
#define NPAD_LX 128
#define KLSTM 608        // [wi 0..80 | pad | h 88..599 | pad]
#define H_OFF 88
#define NLSTM 2048

// GEMM tiling (fp16 mma.m16n8k16)
#define BM 128
#define BN 128
#define BK 32
#define ASTH 40                          // smem row stride in halves (80B)
#define STGH (128 * ASTH)                // halves per stage sub-buffer = 5120
#define DSMEM_BYTES (3 * 2 * STGH * 2)   // 61440
#define SST 72                           // fp32 staging row stride (epilogue)

// ---------------- helpers ----------------
__device__ __forceinline__ uint32_t smem_u32(const void* p) {
    uint32_t a;
    asm("{ .reg .u64 t; cvta.to.shared.u64 t, %1; cvt.u32.u64 %0, t; }" : "=r"(a) : "l"(p));
    return a;
}
#define CP_ASYNC16(dst, src) \
    asm volatile("cp.async.cg.shared.global [%0], [%1], 16;" :: "r"(dst), "l"(src))
#define CP_COMMIT() asm volatile("cp.async.commit_group;" ::: "memory")
#define CP_WAIT1()  asm volatile("cp.async.wait_group 1;" ::: "memory")
#define CP_WAIT0()  asm volatile("cp.async.wait_group 0;" ::: "memory")

#define LDMATRIX_X4(r0, r1, r2, r3, addr) \
    asm volatile("ldmatrix.sync.aligned.m8n8.x4.shared.b16 {%0,%1,%2,%3}, [%4];" \
        : "=r"(r0), "=r"(r1), "=r"(r2), "=r"(r3) : "r"(addr))

__device__ __forceinline__ void mma_fp16(float c[4], const uint32_t a[4],
                                         uint32_t b0, uint32_t b1) {
    asm volatile(
        "mma.sync.aligned.m16n8k16.row.col.f32.f16.f16.f32 "
        "{%0,%1,%2,%3}, {%4,%5,%6,%7}, {%8,%9}, {%0,%1,%2,%3};"
        : "+f"(c[0]), "+f"(c[1]), "+f"(c[2]), "+f"(c[3])
        : "r"(a[0]), "r"(a[1]), "r"(a[2]), "r"(a[3]), "r"(b0), "r"(b1));
}

// explicit MUFU-based transcendentals
__device__ __forceinline__ float ex2f_(float x) {
    float y; asm("ex2.approx.f32 %0, %1;" : "=f"(y) : "f"(x)); return y;
}
__device__ __forceinline__ float rcpf_(float x) {
    float y; asm("rcp.approx.f32 %0, %1;" : "=f"(y) : "f"(x)); return y;
}
#define LOG2E_ 1.4426950408889634f
__device__ __forceinline__ float sigf_(float x) {
    return rcpf_(1.f + ex2f_(-LOG2E_ * x));
}
__device__ __forceinline__ float tanhf_(float x) {
    return 2.f * rcpf_(1.f + ex2f_(-2.f * LOG2E_ * x)) - 1.f;
}

// ---------------- device scratch ----------------
__device__ __align__(16) __half g_Apad  [(size_t)BB * KCONV];
__device__ __align__(16) __half g_WeffT [(size_t)NCONV * KCONV];
__device__ float  g_Cconv [(size_t)BB * NCONV];   // stores tanh(conv + bias)
__device__ __align__(16) float g_biasn [NCONV];
__device__ float  g_xstat [(size_t)BB * FPAD];
__device__ float  g_WxT   [(size_t)FPAD * NPAD_LX];
__device__ float  g_Lx    [(size_t)BB * NPAD_LX];
__device__ float  g_rWx   [NPAD_LX];
__device__ float  g_ystat [(size_t)BB * INPC];
__device__ __align__(16) __half g_WcombT[(size_t)NLSTM * KLSTM];
__device__ float  g_bcomb [NLSTM];
__device__ __align__(16) __half g_Acomb [2][(size_t)BB * KLSTM];
__device__ float  g_cbuf  [(size_t)BB * HH];

// ---------------- prep kernels ----------------
__global__ void k_zero_state() {
    int idx = blockIdx.x * blockDim.x + threadIdx.x;
    if (idx < BB * KLSTM / 2) {
        ((uint32_t*)&g_Acomb[0][0])[idx] = 0u;
        ((uint32_t*)&g_Acomb[1][0])[idx] = 0u;
    }
    if (idx < BB * HH)   g_cbuf[idx]  = 0.f;
    if (idx < BB * FPAD) g_xstat[idx] = 0.f;
}
__global__ void k_pad_input(const float* __restrict__ in) {
    int idx = blockIdx.x * blockDim.x + threadIdx.x;
    if (idx >= BB * KCONV) return;
    int b = idx / KCONV, k = idx - b * KCONV;
    g_Apad[idx] = (k < 729) ? __float2half(in[(size_t)b * 729 + k]) : __half(0.f);
}
__global__ void k_build_wefft(const float* __restrict__ w3, const float* __restrict__ w5,
                              const float* __restrict__ w7, const float* __restrict__ w11,
                              const float* __restrict__ w13) {
    int idx = blockIdx.x * blockDim.x + threadIdx.x;
    if (idx >= NCONV * KCONV) return;
    int n = idx / KCONV, k = idx - n * KCONV;
    float v = 0.f;
    if (k < 729 && n < 3645) {
        int s = k / 81, i = k - s * 81;
        int f = n / 9, t = n - f * 9;
        int kidx = f / 81, o = f - kidx * 81;
        const int ksz[5] = {3, 5, 7, 11, 13};
        const float* wp = (kidx == 0) ? w3 : (kidx == 1) ? w5 : (kidx == 2) ? w7
                         : (kidx == 3) ? w11 : w13;
        int kw = ksz[kidx];
        int j = s - t + ((kw - 1) >> 1);
        if (j >= 0 && j < kw) v = wp[(o * 81 + i) * kw + j];
    }
    g_WeffT[idx] = __float2half(v);
}
__global__ void k_build_biasn(const float* __restrict__ b3, const float* __restrict__ b5,
                              const float* __restrict__ b7, const float* __restrict__ b11,
                              const float* __restrict__ b13) {
    int n = blockIdx.x * blockDim.x + threadIdx.x;
    if (n >= NCONV) return;
    float v = 0.f;
    if (n < 3645) {
        int f = n / 9;
        int kidx = f / 81, o = f - kidx * 81;
        v = (kidx == 0) ? b3[o] : (kidx == 1) ? b5[o] : (kidx == 2) ? b7[o]
           : (kidx == 3) ? b11[o] : b13[o];
    }
    g_biasn[n] = v;
}
__global__ void k_build_wxt(const float* __restrict__ regrW) {
    int idx = blockIdx.x * blockDim.x + threadIdx.x;
    if (idx >= FPAD * NPAD_LX) return;
    int f = idx / NPAD_LX, o = idx - f * NPAD_LX;
    g_WxT[idx] = (f < 405 && o < 81) ? regrW[o * 486 + f] : 0.f;
}
__global__ void k_build_wcombt(const float* __restrict__ Wih, const float* __restrict__ Whh,
                               const float* __restrict__ bih, const float* __restrict__ bhh) {
    int idx = blockIdx.x * blockDim.x + threadIdx.x;
    if (idx >= NLSTM * KLSTM) return;
    int n = idx / KLSTM, k = idx - n * KLSTM;
    int g = n & 3, j = n >> 2;
    int r = g * HH + j;
    float v = 0.f;
    if (k < 81)                            v = Wih[(size_t)r * 81 + k];
    else if (k >= H_OFF && k < H_OFF + HH) v = Whh[(size_t)r * HH + (k - H_OFF)];
    g_WcombT[idx] = __float2half(v);
    if (k == 0) g_bcomb[n] = bih[r] + bhh[r];
}
__global__ void k_ystat(const float* __restrict__ in, const float* __restrict__ cosw,
                        const float* __restrict__ cosb) {
    int idx = blockIdx.x * blockDim.x + threadIdx.x;
    if (idx >= BB * INPC) return;
    int b = idx / INPC, i = idx - b * INPC;
    float a = cosb[0];
#pragma unroll
    for (int s = 0; s < TT; s++) a += in[(size_t)b * 729 + s * 81 + i] * cosw[1024 + s];
    g_ystat[idx] = a;
}
__global__ void k_rwx(const float* __restrict__ regrW) {
    int o = threadIdx.x;
    if (o >= NPAD_LX) return;
    float a = 0.f;
    if (o < 81)
        for (int f = 0; f < 405; f++) a += regrW[o * 486 + f];
    g_rWx[o] = a;
}
// Cconv already holds tanh(conv+bias); just the 9-tap weighted sum remains.
__global__ void k_reduce_x(const float* __restrict__ aconvw, const float* __restrict__ aconvb) {
    int idx = blockIdx.x * blockDim.x + threadIdx.x;
    if (idx >= BB * 405) return;
    int b = idx / 405, f = idx - b * 405;
    const float* crow = &g_Cconv[(size_t)b * NCONV + f * 9];
    float acc = aconvb[0];
#pragma unroll
    for (int t = 0; t < TT; t++) acc += crow[t] * aconvw[1024 + t];
    g_xstat[(size_t)b * FPAD + f] = acc;
}

// ---------------- small fp32 GEMM (Lx only) ----------------
__device__ __forceinline__ void gemm_tile(const float* __restrict__ A,
                                          const float* __restrict__ B,
                                          int N, int K, float acc[8][8]) {
    __shared__ float As[8][128];
    __shared__ float Bs[8][128];
    const int tid = threadIdx.x;
    const int bm = blockIdx.y * 128, bn = blockIdx.x * 128;
    const int aRow = tid >> 1, aCol = (tid & 1) << 2;
    const int bRow = tid >> 5, bCol = (tid & 31) << 2;
    const int tx = tid & 15, ty = tid >> 4;
    const float* Ap = A + (size_t)(bm + aRow) * K + aCol;
    const float* Bp = B + (size_t)bRow * N + bn + bCol;
    for (int k0 = 0; k0 < K; k0 += 8) {
        float4 av = *(const float4*)(Ap + k0);
        float4 bv = *(const float4*)(Bp + (size_t)k0 * N);
        As[aCol + 0][aRow] = av.x; As[aCol + 1][aRow] = av.y;
        As[aCol + 2][aRow] = av.z; As[aCol + 3][aRow] = av.w;
        *(float4*)&Bs[bRow][bCol] = bv;
        __syncthreads();
#pragma unroll
        for (int kk = 0; kk < 8; kk++) {
            float a[8], b[8];
            *(float4*)&a[0] = *(const float4*)&As[kk][ty << 2];
            *(float4*)&a[4] = *(const float4*)&As[kk][(ty << 2) + 64];
            *(float4*)&b[0] = *(const float4*)&Bs[kk][tx << 2];
            *(float4*)&b[4] = *(const float4*)&Bs[kk][(tx << 2) + 64];
#pragma unroll
            for (int im = 0; im < 8; im++)
#pragma unroll
                for (int in = 0; in < 8; in++)
                    acc[im][in] += a[im] * b[in];
        }
        __syncthreads();
    }
}
__global__ __launch_bounds__(256) void k_sgemm_lx() {
    float acc[8][8];
#pragma unroll
    for (int i = 0; i < 8; i++)
#pragma unroll
        for (int j = 0; j < 8; j++) acc[i][j] = 0.f;
    gemm_tile(g_xstat, g_WxT, NPAD_LX, FPAD, acc);
    const int tid = threadIdx.x;
    const int tx = tid & 15, ty = tid >> 4;
    const int bm = blockIdx.y * 128, bn = blockIdx.x * 128;
#pragma unroll
    for (int hm = 0; hm < 2; hm++)
#pragma unroll
        for (int i = 0; i < 4; i++) {
            int m = bm + (ty << 2) + hm * 64 + i;
            float4 v0 = make_float4(acc[hm*4+i][0], acc[hm*4+i][1], acc[hm*4+i][2], acc[hm*4+i][3]);
            float4 v1 = make_float4(acc[hm*4+i][4], acc[hm*4+i][5], acc[hm*4+i][6], acc[hm*4+i][7]);
            *(float4*)&g_Lx[(size_t)m * NPAD_LX + bn + (tx << 2)]      = v0;
            *(float4*)&g_Lx[(size_t)m * NPAD_LX + bn + 64 + (tx << 2)] = v1;
        }
}

// ---------------- fp16 mma GEMM engine ----------------
template <int KEL>
__device__ __forceinline__ void ld_stage(const __half* __restrict__ Ab,
                                         const __half* __restrict__ Bb,
                                         __half* As, __half* Bs, int kb, int tid) {
    const __half* ag = Ab + kb * BK;
    const __half* bg = Bb + kb * BK;
#pragma unroll
    for (int it = 0; it < 2; it++) {
        int chunk = tid + it * 256;
        int r = chunk >> 2, ch = chunk & 3;
        CP_ASYNC16(smem_u32(As + r * ASTH + ch * 8), ag + (size_t)r * KEL + ch * 8);
    }
#pragma unroll
    for (int it = 0; it < 2; it++) {
        int chunk = tid + it * 256;
        int r = chunk >> 2, ch = chunk & 3;
        CP_ASYNC16(smem_u32(Bs + r * ASTH + ch * 8), bg + (size_t)r * KEL + ch * 8);
    }
}

template <int KEL, int KB>
__device__ __forceinline__ void mma_mainloop(const __half* __restrict__ Ab,
                                             const __half* __restrict__ Bb,
                                             float acc[4][4][4], __half* sm) {
    const int tid = threadIdx.x;
    const int warp = tid >> 5, lane = tid & 31;
    const int wm = warp & 1, wn = warp >> 1;

    ld_stage<KEL>(Ab, Bb, sm,            sm + STGH,     0, tid);
    CP_COMMIT();
    ld_stage<KEL>(Ab, Bb, sm + 2 * STGH, sm + 3 * STGH, 1, tid);
    CP_COMMIT();

    const int ra  = wm * 64 + (lane & 15);
    const int ca  = (lane >> 4) << 3;
    const int rb  = wn * 32 + (lane & 7) + ((lane >> 4) << 3);
    const int cb  = ((lane >> 3) & 1) << 3;

    for (int kb = 0; kb < KB; kb++) {
        if (kb < KB - 1) { CP_WAIT1(); } else { CP_WAIT0(); }
        __syncthreads();
        if (kb + 2 < KB) {
            __half* dst = sm + ((kb + 2) % 3) * 2 * STGH;
            ld_stage<KEL>(Ab, Bb, dst, dst + STGH, kb + 2, tid);
            CP_COMMIT();
        }
        const __half* As = sm + (kb % 3) * 2 * STGH;
        const __half* Bs = As + STGH;
#pragma unroll
        for (int ks = 0; ks < 2; ks++) {
            uint32_t af[4][4];
#pragma unroll
            for (int mt = 0; mt < 4; mt++) {
                uint32_t addr = smem_u32(&As[(ra + mt * 16) * ASTH + ks * 16 + ca]);
                LDMATRIX_X4(af[mt][0], af[mt][1], af[mt][2], af[mt][3], addr);
            }
#pragma unroll
            for (int ntp = 0; ntp < 2; ntp++) {
                uint32_t b0, b1, b2, b3;
                uint32_t addr = smem_u32(&Bs[(rb + ntp * 16) * ASTH + ks * 16 + cb]);
                LDMATRIX_X4(b0, b1, b2, b3, addr);
#pragma unroll
                for (int mt = 0; mt < 4; mt++)
                    mma_fp16(acc[mt][2 * ntp], af[mt], b0, b1);
#pragma unroll
                for (int mt = 0; mt < 4; mt++)
                    mma_fp16(acc[mt][2 * ntp + 1], af[mt], b2, b3);
            }
        }
        __syncthreads();
    }
}

// stage pass-p C columns (nt = 2p, 2p+1) into fp32 smem [128][SST]
__device__ __forceinline__ void stage_pass(float* sf, const float acc[4][4][4],
                                           int p, int lane, int wm, int wn) {
#pragma unroll
    for (int mt = 0; mt < 4; mt++)
#pragma unroll
        for (int ntl = 0; ntl < 2; ntl++) {
            int nt = 2 * p + ntl;
            int r = wm * 64 + mt * 16 + (lane >> 2);
            int cl = wn * 16 + ntl * 8 + 2 * (lane & 3);
            *(float2*)&sf[r * SST + cl]       = make_float2(acc[mt][nt][0], acc[mt][nt][1]);
            *(float2*)&sf[(r + 8) * SST + cl] = make_float2(acc[mt][nt][2], acc[mt][nt][3]);
        }
}

// ---------------- conv GEMM + fused bias/tanh epilogue ----------------
__global__ __launch_bounds__(256, 3) void k_mma_conv() {
    extern __shared__ __half sm[];
    const int tid = threadIdx.x;
    const int lane = tid & 31, warp = tid >> 5;
    const int wm = warp & 1, wn = warp >> 1;
    const int bm = blockIdx.y * BM, bn = blockIdx.x * BN;
    float acc[4][4][4];
#pragma unroll
    for (int i = 0; i < 4; i++)
#pragma unroll
        for (int j = 0; j < 4; j++)
#pragma unroll
            for (int q = 0; q < 4; q++) acc[i][j][q] = 0.f;
    mma_mainloop<KCONV, KCONV / BK>(g_Apad + (size_t)bm * KCONV,
                                    g_WeffT + (size_t)bn * KCONV, acc, sm);

    float* sf = (float*)sm;
    const int row = tid >> 1, m = bm + row;
#pragma unroll
    for (int p = 0; p < 2; p++) {
        if (p) __syncthreads();
        stage_pass(sf, acc, p, lane, wm, wn);
        __syncthreads();
#pragma unroll
        for (int g = 0; g < 2; g++) {
            int wnp = (tid & 1) * 2 + g;
            int cg0 = bn + wnp * 32 + p * 16;
            int cl0 = wnp * 16;
#pragma unroll
            for (int q4 = 0; q4 < 4; q4++) {
                float4 v = *(const float4*)&sf[row * SST + cl0 + 4 * q4];
                float4 bi = *(const float4*)&g_biasn[cg0 + 4 * q4];
                v.x = tanhf_(v.x + bi.x); v.y = tanhf_(v.y + bi.y);
                v.z = tanhf_(v.z + bi.z); v.w = tanhf_(v.w + bi.w);
                *(float4*)&g_Cconv[(size_t)m * NCONV + cg0 + 4 * q4] = v;
            }
        }
    }
}

// ---------------- LSTM GEMM + fused gate epilogue (smem-staged) ----------------
__global__ __launch_bounds__(256, 3) void k_mma_lstm(float* __restrict__ out_enc, int t,
                                                     int bin, int bout) {
    extern __shared__ __half sm[];
    const int tid = threadIdx.x;
    const int lane = tid & 31, warp = tid >> 5;
    const int wm = warp & 1, wn = warp >> 1;
    const int bm = blockIdx.y * BM, bn = blockIdx.x * BN;
    float acc[4][4][4];
#pragma unroll
    for (int i = 0; i < 4; i++)
#pragma unroll
        for (int j = 0; j < 4; j++)
#pragma unroll
            for (int q = 0; q < 4; q++) acc[i][j][q] = 0.f;
    mma_mainloop<KLSTM, KLSTM / BK>(g_Acomb[bin] + (size_t)bm * KLSTM,
                                    g_WcombT + (size_t)bn * KLSTM, acc, sm);

    __half* Aout = g_Acomb[bout];
    float* sf = (float*)sm;
    const int row = tid >> 1, m = bm + row;
#pragma unroll
    for (int p = 0; p < 2; p++) {
        if (p) __syncthreads();
        stage_pass(sf, acc, p, lane, wm, wn);
        __syncthreads();
#pragma unroll
        for (int g = 0; g < 2; g++) {
            int wnp = (tid & 1) * 2 + g;
            int cg0 = bn + wnp * 32 + p * 16;
            int cl0 = wnp * 16;
            int u0 = cg0 >> 2;
            float gv[16], bb[16];
#pragma unroll
            for (int q4 = 0; q4 < 4; q4++) {
                *(float4*)&gv[4 * q4] = *(const float4*)&sf[row * SST + cl0 + 4 * q4];
                *(float4*)&bb[4 * q4] = *(const float4*)&g_bcomb[cg0 + 4 * q4];
            }
            float cold[4];
            *(float4*)&cold[0] = *(const float4*)&g_cbuf[(size_t)m * HH + u0];
            float c4[4], h4[4];
            __half hh[4];
#pragma unroll
            for (int q = 0; q < 4; q++) {
                float iv = sigf_(gv[4 * q + 0] + bb[4 * q + 0]);
                float fv = sigf_(gv[4 * q + 1] + bb[4 * q + 1]);
                float gg = tanhf_(gv[4 * q + 2] + bb[4 * q + 2]);
                float ov = sigf_(gv[4 * q + 3] + bb[4 * q + 3]);
                float c2 = fv * cold[q] + iv * gg;
                c4[q] = c2;
                h4[q] = ov * tanhf_(c2);
                hh[q] = __float2half(h4[q]);
            }
            *(float4*)&g_cbuf[(size_t)m * HH + u0] = *(float4*)&c4[0];
            *(float4*)&out_enc[(size_t)m * (TT * HH) + t * HH + u0] = *(float4*)&h4[0];
            *(uint2*)&Aout[(size_t)m * KLSTM + H_OFF + u0] = *(uint2*)&hh[0];
        }
    }
}

// ---------------- per-step attention (warp handles 4 batches) ----------------
__global__ __launch_bounds__(256) void k_att(const float* __restrict__ input,
                                             const float* __restrict__ regrW,
                                             const float* __restrict__ regrb,
                                             const float* __restrict__ aconvw,
                                             const float* __restrict__ acosw,
                                             int t, int bin,
                                             float* __restrict__ out_w,
                                             const float* __restrict__ out_enc) {
    __shared__ float Wy[81 * 81];
    __shared__ float ysh[8][81];
    const int tid = threadIdx.x;
    for (int idx = tid; idx < 81 * 81; idx += 256) {
        int o = idx / 81, i = idx - o * 81;
        Wy[idx] = regrW[o * 486 + 405 + i];
    }
    __syncthreads();

    const int w = tid >> 5, l = tid & 31;
    __half* Ain = g_Acomb[bin];

    for (int bi = 0; bi < 4; bi++) {
        const int b = blockIdx.x * 32 + w * 4 + bi;
        const float* hprev = out_enc + (size_t)b * (TT * HH) + (t - 1) * HH;
        const float* c = g_cbuf + (size_t)b * HH;

        float sx = 0.f, sy = 0.f;
        if (t > 0) {
            for (int k = l; k < HH; k += 32) {
                float hv = hprev[k], cv = c[k];
                sx += hv * aconvw[k] + cv * aconvw[512 + k];
                sy += hv * acosw[k] + cv * acosw[512 + k];
            }
#pragma unroll
            for (int off = 16; off; off >>= 1) {
                sx += __shfl_xor_sync(0xffffffffu, sx, off);
                sy += __shfl_xor_sync(0xffffffffu, sy, off);
            }
        }
        for (int i = l; i < 81; i += 32)
            ysh[w][i] = __cosf(g_ystat[(size_t)b * 81 + i] + sy);
        __syncwarp();

        float lgv[3];
#pragma unroll
        for (int q = 0; q < 3; q++) {
            int o = l + q * 32;
            float acc = -1e30f;
            if (o < 81) {
                acc = g_Lx[(size_t)b * NPAD_LX + o] + sx * g_rWx[o] + regrb[o];
                const float* wrow = &Wy[o * 81];
#pragma unroll 9
                for (int i = 0; i < 81; i++) acc += ysh[w][i] * wrow[i];
            }
            lgv[q] = acc;
        }
        float mx = fmaxf(fmaxf(lgv[0], lgv[1]), lgv[2]);
#pragma unroll
        for (int off = 16; off; off >>= 1) mx = fmaxf(mx, __shfl_xor_sync(0xffffffffu, mx, off));
        float e[3], ssum = 0.f;
#pragma unroll
        for (int q = 0; q < 3; q++) {
            e[q] = (l + q * 32 < 81) ? __expf(lgv[q] - mx) : 0.f;
            ssum += e[q];
        }
#pragma unroll
        for (int off = 16; off; off >>= 1) ssum += __shfl_xor_sync(0xffffffffu, ssum, off);
        float inv = 1.f / ssum;
#pragma unroll
        for (int q = 0; q < 3; q++) {
            int o = l + q * 32;
            if (o < 81) {
                float wi = e[q] * inv * input[(size_t)b * 729 + t * 81 + o];
                Ain[(size_t)b * KLSTM + o] = __float2half(wi);
                out_w[(size_t)b * 729 + t * 81 + o] = wi;
            }
        }
        __syncwarp();
    }
}

// ---------------- launch ----------------
extern "C" void kernel_launch(void* const* d_in, const int* in_sizes, int n_in,
                              void* d_out, int out_size) {
    const float* input  = (const float*)d_in[0];
    const float* w3  = (const float*)d_in[1];  const float* b3  = (const float*)d_in[2];
    const float* w5  = (const float*)d_in[3];  const float* b5  = (const float*)d_in[4];
    const float* w7  = (const float*)d_in[5];  const float* b7  = (const float*)d_in[6];
    const float* w11 = (const float*)d_in[7];  const float* b11 = (const float*)d_in[8];
    const float* w13 = (const float*)d_in[9];  const float* b13 = (const float*)d_in[10];
    const float* aconvw = (const float*)d_in[11]; const float* aconvb = (const float*)d_in[12];
    const float* acosw  = (const float*)d_in[13]; const float* acosb  = (const float*)d_in[14];
    const float* regrW  = (const float*)d_in[15]; const float* regrb  = (const float*)d_in[16];
    const float* Wih = (const float*)d_in[17]; const float* Whh = (const float*)d_in[18];
    const float* bih = (const float*)d_in[19]; const float* bhh = (const float*)d_in[20];

    float* out_w   = (float*)d_out;
    float* out_enc = out_w + (size_t)BB * TT * INPC;

    cudaFuncSetAttribute(k_mma_conv, cudaFuncAttributeMaxDynamicSharedMemorySize, DSMEM_BYTES);
    cudaFuncSetAttribute(k_mma_lstm, cudaFuncAttributeMaxDynamicSharedMemorySize, DSMEM_BYTES);

    const int TH = 256;
    k_zero_state<<<(BB * KLSTM + TH - 1) / TH, TH>>>();
    k_pad_input<<<(BB * KCONV + TH - 1) / TH, TH>>>(input);
    k_build_wefft<<<(NCONV * KCONV + TH - 1) / TH, TH>>>(w3, w5, w7, w11, w13);
    k_build_biasn<<<(NCONV + TH - 1) / TH, TH>>>(b3, b5, b7, b11, b13);
    dim3 gconv(NCONV / BN, BB / BM);
    k_mma_conv<<<gconv, 256, DSMEM_BYTES>>>();

    k_build_wxt<<<(FPAD * NPAD_LX + TH - 1) / TH, TH>>>(regrW);
    k_build_wcombt<<<(NLSTM * KLSTM + TH - 1) / TH, TH>>>(Wih, Whh, bih, bhh);
    k_ystat<<<(BB * INPC + TH - 1) / TH, TH>>>(input, acosw, acosb);
    k_rwx<<<1, NPAD_LX>>>(regrW);
    k_reduce_x<<<(BB * 405 + TH - 1) / TH, TH>>>(aconvw, aconvb);
    dim3 glx(NPAD_LX / 128, BB / 128);
    k_sgemm_lx<<<glx, 256>>>();

    dim3 glstm(NLSTM / BN, BB / BM);
    for (int t = 0; t < TT; t++) {
        int bin = t & 1, bout = (t + 1) & 1;
        k_att<<<BB / 32, 256>>>(input, regrW, regrb, aconvw, acosw, t, bin, out_w, out_enc);
        k_mma_lstm<<<glstm, 256, DSMEM_BYTES>>>(out_enc, t, bin, bout);
    }
}

// round 8
// speedup vs baseline: 1.4754x; 1.4754x over previous
#include <cuda_runtime.h>
#include <cuda_fp16.h>
#include <math.h>
#include <stdint.h>
#include <stddef.h>

// ---------------- problem constants ----------------
#define BB    8192
#define TT    9
#define INPC  81
#define HH    512

#define KCONV 736        // 729 padded (mult of 32)
#define NCONV 3840       // 3645 padded (mult of 128)
#define FPAD  416
#define NPAD_LX 128
#define KLSTM 608        // [wi 0..80 | pad | h 88..599 | pad]
#define H_OFF 88
#define NLSTM 2048

// GEMM tiling (fp16 mma.m16n8k16)
#define BM 128
#define BN 128
#define BK 32
#define ASTH 40                          // smem row stride in halves (80B)
#define STGH (128 * ASTH)                // halves per stage sub-buffer = 5120
#define DSMEM_BYTES (3 * 2 * STGH * 2)   // 61440
#define SST 72                           // fp32 staging row stride (epilogue)

// ---------------- helpers ----------------
__device__ __forceinline__ uint32_t smem_u32(const void* p) {
    uint32_t a;
    asm("{ .reg .u64 t; cvta.to.shared.u64 t, %1; cvt.u32.u64 %0, t; }" : "=r"(a) : "l"(p));
    return a;
}
#define CP_ASYNC16(dst, src) \
    asm volatile("cp.async.cg.shared.global [%0], [%1], 16;" :: "r"(dst), "l"(src))
#define CP_COMMIT() asm volatile("cp.async.commit_group;" ::: "memory")
#define CP_WAIT1()  asm volatile("cp.async.wait_group 1;" ::: "memory")
#define CP_WAIT0()  asm volatile("cp.async.wait_group 0;" ::: "memory")

#define LDMATRIX_X4(r0, r1, r2, r3, addr) \
    asm volatile("ldmatrix.sync.aligned.m8n8.x4.shared.b16 {%0,%1,%2,%3}, [%4];" \
        : "=r"(r0), "=r"(r1), "=r"(r2), "=r"(r3) : "r"(addr))

__device__ __forceinline__ void mma_fp16(float c[4], const uint32_t a[4],
                                         uint32_t b0, uint32_t b1) {
    asm volatile(
        "mma.sync.aligned.m16n8k16.row.col.f32.f16.f16.f32 "
        "{%0,%1,%2,%3}, {%4,%5,%6,%7}, {%8,%9}, {%0,%1,%2,%3};"
        : "+f"(c[0]), "+f"(c[1]), "+f"(c[2]), "+f"(c[3])
        : "r"(a[0]), "r"(a[1]), "r"(a[2]), "r"(a[3]), "r"(b0), "r"(b1));
}

// explicit MUFU-based transcendentals
__device__ __forceinline__ float ex2f_(float x) {
    float y; asm("ex2.approx.f32 %0, %1;" : "=f"(y) : "f"(x)); return y;
}
__device__ __forceinline__ float rcpf_(float x) {
    float y; asm("rcp.approx.f32 %0, %1;" : "=f"(y) : "f"(x)); return y;
}
#define LOG2E_ 1.4426950408889634f
__device__ __forceinline__ float sigf_(float x) {
    return rcpf_(1.f + ex2f_(-LOG2E_ * x));
}
__device__ __forceinline__ float tanhf_(float x) {
    return 2.f * rcpf_(1.f + ex2f_(-2.f * LOG2E_ * x)) - 1.f;
}

// ---------------- device scratch ----------------
__device__ __align__(16) __half g_Apad  [(size_t)BB * KCONV];
__device__ __align__(16) __half g_WeffT [(size_t)NCONV * KCONV];
__device__ float  g_Cconv [(size_t)BB * NCONV];   // stores tanh(conv + bias)
__device__ __align__(16) float g_biasn [NCONV];
__device__ float  g_xstat [(size_t)BB * FPAD];
__device__ float  g_WxT   [(size_t)FPAD * NPAD_LX];
__device__ float  g_Lx    [(size_t)BB * NPAD_LX];
__device__ float  g_rWx   [NPAD_LX];
__device__ float  g_ystat [(size_t)BB * INPC];
__device__ __align__(16) __half g_WcombT[(size_t)NLSTM * KLSTM];
__device__ float  g_bcomb [NLSTM];
__device__ __align__(16) __half g_Acomb [2][(size_t)BB * KLSTM];
__device__ float  g_cbuf  [(size_t)BB * HH];

// ---------------- prep kernels ----------------
__global__ void k_zero_state() {
    int idx = blockIdx.x * blockDim.x + threadIdx.x;
    if (idx < BB * KLSTM / 2) {
        ((uint32_t*)&g_Acomb[0][0])[idx] = 0u;
        ((uint32_t*)&g_Acomb[1][0])[idx] = 0u;
    }
    if (idx < BB * HH)   g_cbuf[idx]  = 0.f;
    if (idx < BB * FPAD) g_xstat[idx] = 0.f;
}
__global__ void k_pad_input(const float* __restrict__ in) {
    int idx = blockIdx.x * blockDim.x + threadIdx.x;
    if (idx >= BB * KCONV) return;
    int b = idx / KCONV, k = idx - b * KCONV;
    g_Apad[idx] = (k < 729) ? __float2half(in[(size_t)b * 729 + k]) : __half(0.f);
}
__global__ void k_build_wefft(const float* __restrict__ w3, const float* __restrict__ w5,
                              const float* __restrict__ w7, const float* __restrict__ w11,
                              const float* __restrict__ w13) {
    int idx = blockIdx.x * blockDim.x + threadIdx.x;
    if (idx >= NCONV * KCONV) return;
    int n = idx / KCONV, k = idx - n * KCONV;
    float v = 0.f;
    if (k < 729 && n < 3645) {
        int s = k / 81, i = k - s * 81;
        int f = n / 9, t = n - f * 9;
        int kidx = f / 81, o = f - kidx * 81;
        const int ksz[5] = {3, 5, 7, 11, 13};
        const float* wp = (kidx == 0) ? w3 : (kidx == 1) ? w5 : (kidx == 2) ? w7
                         : (kidx == 3) ? w11 : w13;
        int kw = ksz[kidx];
        int j = s - t + ((kw - 1) >> 1);
        if (j >= 0 && j < kw) v = wp[(o * 81 + i) * kw + j];
    }
    g_WeffT[idx] = __float2half(v);
}
__global__ void k_build_biasn(const float* __restrict__ b3, const float* __restrict__ b5,
                              const float* __restrict__ b7, const float* __restrict__ b11,
                              const float* __restrict__ b13) {
    int n = blockIdx.x * blockDim.x + threadIdx.x;
    if (n >= NCONV) return;
    float v = 0.f;
    if (n < 3645) {
        int f = n / 9;
        int kidx = f / 81, o = f - kidx * 81;
        v = (kidx == 0) ? b3[o] : (kidx == 1) ? b5[o] : (kidx == 2) ? b7[o]
           : (kidx == 3) ? b11[o] : b13[o];
    }
    g_biasn[n] = v;
}
__global__ void k_build_wxt(const float* __restrict__ regrW) {
    int idx = blockIdx.x * blockDim.x + threadIdx.x;
    if (idx >= FPAD * NPAD_LX) return;
    int f = idx / NPAD_LX, o = idx - f * NPAD_LX;
    g_WxT[idx] = (f < 405 && o < 81) ? regrW[o * 486 + f] : 0.f;
}
__global__ void k_build_wcombt(const float* __restrict__ Wih, const float* __restrict__ Whh,
                               const float* __restrict__ bih, const float* __restrict__ bhh) {
    int idx = blockIdx.x * blockDim.x + threadIdx.x;
    if (idx >= NLSTM * KLSTM) return;
    int n = idx / KLSTM, k = idx - n * KLSTM;
    int g = n & 3, j = n >> 2;
    int r = g * HH + j;
    float v = 0.f;
    if (k < 81)                            v = Wih[(size_t)r * 81 + k];
    else if (k >= H_OFF && k < H_OFF + HH) v = Whh[(size_t)r * HH + (k - H_OFF)];
    g_WcombT[idx] = __float2half(v);
    if (k == 0) g_bcomb[n] = bih[r] + bhh[r];
}
__global__ void k_ystat(const float* __restrict__ in, const float* __restrict__ cosw,
                        const float* __restrict__ cosb) {
    int idx = blockIdx.x * blockDim.x + threadIdx.x;
    if (idx >= BB * INPC) return;
    int b = idx / INPC, i = idx - b * INPC;
    float a = cosb[0];
#pragma unroll
    for (int s = 0; s < TT; s++) a += in[(size_t)b * 729 + s * 81 + i] * cosw[1024 + s];
    g_ystat[idx] = a;
}
__global__ void k_rwx(const float* __restrict__ regrW) {
    int o = threadIdx.x;
    if (o >= NPAD_LX) return;
    float a = 0.f;
    if (o < 81)
        for (int f = 0; f < 405; f++) a += regrW[o * 486 + f];
    g_rWx[o] = a;
}
// Cconv already holds tanh(conv+bias); only the 9-tap weighted sum remains.
__global__ void k_reduce_x(const float* __restrict__ aconvw, const float* __restrict__ aconvb) {
    int idx = blockIdx.x * blockDim.x + threadIdx.x;
    if (idx >= BB * 405) return;
    int b = idx / 405, f = idx - b * 405;
    const float* crow = &g_Cconv[(size_t)b * NCONV + f * 9];
    float acc = aconvb[0];
#pragma unroll
    for (int t = 0; t < TT; t++) acc += crow[t] * aconvw[1024 + t];
    g_xstat[(size_t)b * FPAD + f] = acc;
}

// ---------------- small fp32 GEMM (Lx only) ----------------
__device__ __forceinline__ void gemm_tile(const float* __restrict__ A,
                                          const float* __restrict__ B,
                                          int N, int K, float acc[8][8]) {
    __shared__ float As[8][128];
    __shared__ float Bs[8][128];
    const int tid = threadIdx.x;
    const int bm = blockIdx.y * 128, bn = blockIdx.x * 128;
    const int aRow = tid >> 1, aCol = (tid & 1) << 2;
    const int bRow = tid >> 5, bCol = (tid & 31) << 2;
    const int tx = tid & 15, ty = tid >> 4;
    const float* Ap = A + (size_t)(bm + aRow) * K + aCol;
    const float* Bp = B + (size_t)bRow * N + bn + bCol;
    for (int k0 = 0; k0 < K; k0 += 8) {
        float4 av = *(const float4*)(Ap + k0);
        float4 bv = *(const float4*)(Bp + (size_t)k0 * N);
        As[aCol + 0][aRow] = av.x; As[aCol + 1][aRow] = av.y;
        As[aCol + 2][aRow] = av.z; As[aCol + 3][aRow] = av.w;
        *(float4*)&Bs[bRow][bCol] = bv;
        __syncthreads();
#pragma unroll
        for (int kk = 0; kk < 8; kk++) {
            float a[8], b[8];
            *(float4*)&a[0] = *(const float4*)&As[kk][ty << 2];
            *(float4*)&a[4] = *(const float4*)&As[kk][(ty << 2) + 64];
            *(float4*)&b[0] = *(const float4*)&Bs[kk][tx << 2];
            *(float4*)&b[4] = *(const float4*)&Bs[kk][(tx << 2) + 64];
#pragma unroll
            for (int im = 0; im < 8; im++)
#pragma unroll
                for (int in = 0; in < 8; in++)
                    acc[im][in] += a[im] * b[in];
        }
        __syncthreads();
    }
}
__global__ __launch_bounds__(256) void k_sgemm_lx() {
    float acc[8][8];
#pragma unroll
    for (int i = 0; i < 8; i++)
#pragma unroll
        for (int j = 0; j < 8; j++) acc[i][j] = 0.f;
    gemm_tile(g_xstat, g_WxT, NPAD_LX, FPAD, acc);
    const int tid = threadIdx.x;
    const int tx = tid & 15, ty = tid >> 4;
    const int bm = blockIdx.y * 128, bn = blockIdx.x * 128;
#pragma unroll
    for (int hm = 0; hm < 2; hm++)
#pragma unroll
        for (int i = 0; i < 4; i++) {
            int m = bm + (ty << 2) + hm * 64 + i;
            float4 v0 = make_float4(acc[hm*4+i][0], acc[hm*4+i][1], acc[hm*4+i][2], acc[hm*4+i][3]);
            float4 v1 = make_float4(acc[hm*4+i][4], acc[hm*4+i][5], acc[hm*4+i][6], acc[hm*4+i][7]);
            *(float4*)&g_Lx[(size_t)m * NPAD_LX + bn + (tx << 2)]      = v0;
            *(float4*)&g_Lx[(size_t)m * NPAD_LX + bn + 64 + (tx << 2)] = v1;
        }
}

// ---------------- fp16 mma GEMM engine ----------------
template <int KEL>
__device__ __forceinline__ void ld_stage(const __half* __restrict__ Ab,
                                         const __half* __restrict__ Bb,
                                         __half* As, __half* Bs, int kb, int tid) {
    const __half* ag = Ab + kb * BK;
    const __half* bg = Bb + kb * BK;
#pragma unroll
    for (int it = 0; it < 2; it++) {
        int chunk = tid + it * 256;
        int r = chunk >> 2, ch = chunk & 3;
        CP_ASYNC16(smem_u32(As + r * ASTH + ch * 8), ag + (size_t)r * KEL + ch * 8);
    }
#pragma unroll
    for (int it = 0; it < 2; it++) {
        int chunk = tid + it * 256;
        int r = chunk >> 2, ch = chunk & 3;
        CP_ASYNC16(smem_u32(Bs + r * ASTH + ch * 8), bg + (size_t)r * KEL + ch * 8);
    }
}

template <int KEL, int KB>
__device__ __forceinline__ void mma_mainloop(const __half* __restrict__ Ab,
                                             const __half* __restrict__ Bb,
                                             float acc[4][4][4], __half* sm) {
    const int tid = threadIdx.x;
    const int warp = tid >> 5, lane = tid & 31;
    const int wm = warp & 1, wn = warp >> 1;

    ld_stage<KEL>(Ab, Bb, sm,            sm + STGH,     0, tid);
    CP_COMMIT();
    ld_stage<KEL>(Ab, Bb, sm + 2 * STGH, sm + 3 * STGH, 1, tid);
    CP_COMMIT();

    const int ra  = wm * 64 + (lane & 15);
    const int ca  = (lane >> 4) << 3;
    const int rb  = wn * 32 + (lane & 7) + ((lane >> 4) << 3);
    const int cb  = ((lane >> 3) & 1) << 3;

    for (int kb = 0; kb < KB; kb++) {
        if (kb < KB - 1) { CP_WAIT1(); } else { CP_WAIT0(); }
        __syncthreads();
        if (kb + 2 < KB) {
            __half* dst = sm + ((kb + 2) % 3) * 2 * STGH;
            ld_stage<KEL>(Ab, Bb, dst, dst + STGH, kb + 2, tid);
            CP_COMMIT();
        }
        const __half* As = sm + (kb % 3) * 2 * STGH;
        const __half* Bs = As + STGH;
#pragma unroll
        for (int ks = 0; ks < 2; ks++) {
            uint32_t af[4][4];
#pragma unroll
            for (int mt = 0; mt < 4; mt++) {
                uint32_t addr = smem_u32(&As[(ra + mt * 16) * ASTH + ks * 16 + ca]);
                LDMATRIX_X4(af[mt][0], af[mt][1], af[mt][2], af[mt][3], addr);
            }
#pragma unroll
            for (int ntp = 0; ntp < 2; ntp++) {
                uint32_t b0, b1, b2, b3;
                uint32_t addr = smem_u32(&Bs[(rb + ntp * 16) * ASTH + ks * 16 + cb]);
                LDMATRIX_X4(b0, b1, b2, b3, addr);
#pragma unroll
                for (int mt = 0; mt < 4; mt++)
                    mma_fp16(acc[mt][2 * ntp], af[mt], b0, b1);
#pragma unroll
                for (int mt = 0; mt < 4; mt++)
                    mma_fp16(acc[mt][2 * ntp + 1], af[mt], b2, b3);
            }
        }
        __syncthreads();
    }
}

// stage pass-p C columns (nt = 2p, 2p+1) into fp32 smem [128][SST]
__device__ __forceinline__ void stage_pass(float* sf, const float acc[4][4][4],
                                           int p, int lane, int wm, int wn) {
#pragma unroll
    for (int mt = 0; mt < 4; mt++)
#pragma unroll
        for (int ntl = 0; ntl < 2; ntl++) {
            int nt = 2 * p + ntl;
            int r = wm * 64 + mt * 16 + (lane >> 2);
            int cl = wn * 16 + ntl * 8 + 2 * (lane & 3);
            *(float2*)&sf[r * SST + cl]       = make_float2(acc[mt][nt][0], acc[mt][nt][1]);
            *(float2*)&sf[(r + 8) * SST + cl] = make_float2(acc[mt][nt][2], acc[mt][nt][3]);
        }
}

// ---------------- conv GEMM + fused bias/tanh epilogue ----------------
__global__ __launch_bounds__(256) void k_mma_conv() {
    extern __shared__ __half sm[];
    const int tid = threadIdx.x;
    const int lane = tid & 31, warp = tid >> 5;
    const int wm = warp & 1, wn = warp >> 1;
    const int bm = blockIdx.y * BM, bn = blockIdx.x * BN;
    float acc[4][4][4];
#pragma unroll
    for (int i = 0; i < 4; i++)
#pragma unroll
        for (int j = 0; j < 4; j++)
#pragma unroll
            for (int q = 0; q < 4; q++) acc[i][j][q] = 0.f;
    mma_mainloop<KCONV, KCONV / BK>(g_Apad + (size_t)bm * KCONV,
                                    g_WeffT + (size_t)bn * KCONV, acc, sm);

    float* sf = (float*)sm;
    const int row = tid >> 1, m = bm + row;
#pragma unroll
    for (int p = 0; p < 2; p++) {
        if (p) __syncthreads();
        stage_pass(sf, acc, p, lane, wm, wn);
        __syncthreads();
#pragma unroll
        for (int g = 0; g < 2; g++) {
            int wnp = (tid & 1) * 2 + g;
            int cg0 = bn + wnp * 32 + p * 16;
            int cl0 = wnp * 16;
#pragma unroll
            for (int q4 = 0; q4 < 4; q4++) {
                float4 v = *(const float4*)&sf[row * SST + cl0 + 4 * q4];
                float4 bi = *(const float4*)&g_biasn[cg0 + 4 * q4];
                v.x = tanhf_(v.x + bi.x); v.y = tanhf_(v.y + bi.y);
                v.z = tanhf_(v.z + bi.z); v.w = tanhf_(v.w + bi.w);
                *(float4*)&g_Cconv[(size_t)m * NCONV + cg0 + 4 * q4] = v;
            }
        }
    }
}

// ---------------- LSTM GEMM + fused gate epilogue (smem-staged) ----------------
__global__ __launch_bounds__(256) void k_mma_lstm(float* __restrict__ out_enc, int t,
                                                  int bin, int bout) {
    extern __shared__ __half sm[];
    const int tid = threadIdx.x;
    const int lane = tid & 31, warp = tid >> 5;
    const int wm = warp & 1, wn = warp >> 1;
    const int bm = blockIdx.y * BM, bn = blockIdx.x * BN;
    float acc[4][4][4];
#pragma unroll
    for (int i = 0; i < 4; i++)
#pragma unroll
        for (int j = 0; j < 4; j++)
#pragma unroll
            for (int q = 0; q < 4; q++) acc[i][j][q] = 0.f;
    mma_mainloop<KLSTM, KLSTM / BK>(g_Acomb[bin] + (size_t)bm * KLSTM,
                                    g_WcombT + (size_t)bn * KLSTM, acc, sm);

    __half* Aout = g_Acomb[bout];
    float* sf = (float*)sm;
    const int row = tid >> 1, m = bm + row;
#pragma unroll
    for (int p = 0; p < 2; p++) {
        if (p) __syncthreads();
        stage_pass(sf, acc, p, lane, wm, wn);
        __syncthreads();
#pragma unroll
        for (int g = 0; g < 2; g++) {
            int wnp = (tid & 1) * 2 + g;
            int cg0 = bn + wnp * 32 + p * 16;
            int cl0 = wnp * 16;
            int u0 = cg0 >> 2;
            float gv[16], bb[16];
#pragma unroll
            for (int q4 = 0; q4 < 4; q4++) {
                *(float4*)&gv[4 * q4] = *(const float4*)&sf[row * SST + cl0 + 4 * q4];
                *(float4*)&bb[4 * q4] = *(const float4*)&g_bcomb[cg0 + 4 * q4];
            }
            float cold[4];
            *(float4*)&cold[0] = *(const float4*)&g_cbuf[(size_t)m * HH + u0];
            float c4[4], h4[4];
            __half hh[4];
#pragma unroll
            for (int q = 0; q < 4; q++) {
                float iv = sigf_(gv[4 * q + 0] + bb[4 * q + 0]);
                float fv = sigf_(gv[4 * q + 1] + bb[4 * q + 1]);
                float gg = tanhf_(gv[4 * q + 2] + bb[4 * q + 2]);
                float ov = sigf_(gv[4 * q + 3] + bb[4 * q + 3]);
                float c2 = fv * cold[q] + iv * gg;
                c4[q] = c2;
                h4[q] = ov * tanhf_(c2);
                hh[q] = __float2half(h4[q]);
            }
            *(float4*)&g_cbuf[(size_t)m * HH + u0] = *(float4*)&c4[0];
            *(float4*)&out_enc[(size_t)m * (TT * HH) + t * HH + u0] = *(float4*)&h4[0];
            *(uint2*)&Aout[(size_t)m * KLSTM + H_OFF + u0] = *(uint2*)&hh[0];
        }
    }
}

// ---------------- per-step attention (warp per batch, 8/block) ----------------
__global__ __launch_bounds__(256) void k_att(const float* __restrict__ input,
                                             const float* __restrict__ regrW,
                                             const float* __restrict__ regrb,
                                             const float* __restrict__ aconvw,
                                             const float* __restrict__ acosw,
                                             int t, int bin,
                                             float* __restrict__ out_w,
                                             const float* __restrict__ out_enc) {
    __shared__ float Wy[81 * 81];
    __shared__ float ysh[8][81];
    const int tid = threadIdx.x;
    for (int idx = tid; idx < 81 * 81; idx += 256) {
        int o = idx / 81, i = idx - o * 81;
        Wy[idx] = regrW[o * 486 + 405 + i];
    }
    __syncthreads();

    const int w = tid >> 5, l = tid & 31;
    const int b = blockIdx.x * 8 + w;
    __half* Ain = g_Acomb[bin];
    const float* hprev = out_enc + (size_t)b * (TT * HH) + (t - 1) * HH;
    const float* c = g_cbuf + (size_t)b * HH;

    float sx = 0.f, sy = 0.f;
    if (t > 0) {
        for (int k = l; k < HH; k += 32) {
            float hv = hprev[k], cv = c[k];
            sx += hv * aconvw[k] + cv * aconvw[512 + k];
            sy += hv * acosw[k] + cv * acosw[512 + k];
        }
#pragma unroll
        for (int off = 16; off; off >>= 1) {
            sx += __shfl_xor_sync(0xffffffffu, sx, off);
            sy += __shfl_xor_sync(0xffffffffu, sy, off);
        }
    }
    for (int i = l; i < 81; i += 32)
        ysh[w][i] = __cosf(g_ystat[(size_t)b * 81 + i] + sy);
    __syncwarp();

    float lgv[3];
#pragma unroll
    for (int q = 0; q < 3; q++) {
        int o = l + q * 32;
        float acc = -1e30f;
        if (o < 81) {
            acc = g_Lx[(size_t)b * NPAD_LX + o] + sx * g_rWx[o] + regrb[o];
            const float* wrow = &Wy[o * 81];
#pragma unroll 9
            for (int i = 0; i < 81; i++) acc += ysh[w][i] * wrow[i];
        }
        lgv[q] = acc;
    }
    float mx = fmaxf(fmaxf(lgv[0], lgv[1]), lgv[2]);
#pragma unroll
    for (int off = 16; off; off >>= 1) mx = fmaxf(mx, __shfl_xor_sync(0xffffffffu, mx, off));
    float e[3], ssum = 0.f;
#pragma unroll
    for (int q = 0; q < 3; q++) {
        e[q] = (l + q * 32 < 81) ? __expf(lgv[q] - mx) : 0.f;
        ssum += e[q];
    }
#pragma unroll
    for (int off = 16; off; off >>= 1) ssum += __shfl_xor_sync(0xffffffffu, ssum, off);
    float inv = 1.f / ssum;
#pragma unroll
    for (int q = 0; q < 3; q++) {
        int o = l + q * 32;
        if (o < 81) {
            float wi = e[q] * inv * input[(size_t)b * 729 + t * 81 + o];
            Ain[(size_t)b * KLSTM + o] = __float2half(wi);
            out_w[(size_t)b * 729 + t * 81 + o] = wi;
        }
    }
}

// ---------------- launch ----------------
extern "C" void kernel_launch(void* const* d_in, const int* in_sizes, int n_in,
                              void* d_out, int out_size) {
    const float* input  = (const float*)d_in[0];
    const float* w3  = (const float*)d_in[1];  const float* b3  = (const float*)d_in[2];
    const float* w5  = (const float*)d_in[3];  const float* b5  = (const float*)d_in[4];
    const float* w7  = (const float*)d_in[5];  const float* b7  = (const float*)d_in[6];
    const float* w11 = (const float*)d_in[7];  const float* b11 = (const float*)d_in[8];
    const float* w13 = (const float*)d_in[9];  const float* b13 = (const float*)d_in[10];
    const float* aconvw = (const float*)d_in[11]; const float* aconvb = (const float*)d_in[12];
    const float* acosw  = (const float*)d_in[13]; const float* acosb  = (const float*)d_in[14];
    const float* regrW  = (const float*)d_in[15]; const float* regrb  = (const float*)d_in[16];
    const float* Wih = (const float*)d_in[17]; const float* Whh = (const float*)d_in[18];
    const float* bih = (const float*)d_in[19]; const float* bhh = (const float*)d_in[20];

    float* out_w   = (float*)d_out;
    float* out_enc = out_w + (size_t)BB * TT * INPC;

    cudaFuncSetAttribute(k_mma_conv, cudaFuncAttributeMaxDynamicSharedMemorySize, DSMEM_BYTES);
    cudaFuncSetAttribute(k_mma_lstm, cudaFuncAttributeMaxDynamicSharedMemorySize, DSMEM_BYTES);

    const int TH = 256;
    k_zero_state<<<(BB * KLSTM + TH - 1) / TH, TH>>>();
    k_pad_input<<<(BB * KCONV + TH - 1) / TH, TH>>>(input);
    k_build_wefft<<<(NCONV * KCONV + TH - 1) / TH, TH>>>(w3, w5, w7, w11, w13);
    k_build_biasn<<<(NCONV + TH - 1) / TH, TH>>>(b3, b5, b7, b11, b13);
    dim3 gconv(NCONV / BN, BB / BM);
    k_mma_conv<<<gconv, 256, DSMEM_BYTES>>>();

    k_build_wxt<<<(FPAD * NPAD_LX + TH - 1) / TH, TH>>>(regrW);
    k_build_wcombt<<<(NLSTM * KLSTM + TH - 1) / TH, TH>>>(Wih, Whh, bih, bhh);
    k_ystat<<<(BB * INPC + TH - 1) / TH, TH>>>(input, acosw, acosb);
    k_rwx<<<1, NPAD_LX>>>(regrW);
    k_reduce_x<<<(BB * 405 + TH - 1) / TH, TH>>>(aconvw, aconvb);
    dim3 glx(NPAD_LX / 128, BB / 128);
    k_sgemm_lx<<<glx, 256>>>();

    dim3 glstm(NLSTM / BN, BB / BM);
    for (int t = 0; t < TT; t++) {
        int bin = t & 1, bout = (t + 1) & 1;
        k_att<<<BB / 8, 256>>>(input, regrW, regrb, aconvw, acosw, t, bin, out_w, out_enc);
        k_mma_lstm<<<glstm, 256, DSMEM_BYTES>>>(out_enc, t, bin, bout);
    }
}

// round 9
// speedup vs baseline: 1.5862x; 1.0751x over previous
#include <cuda_runtime.h>
#include <cuda_fp16.h>
#include <math.h>
#include <stdint.h>
#include <stddef.h>

// ---------------- problem constants ----------------
#define BB    8192
#define TT    9
#define INPC  81
#define HH    512

#define KCONV 768        // 729 padded (mult of 64)
#define NCONV 3840       // 3645 padded (mult of 128)
#define FPAD  416
#define NPAD_LX 128
#define KLSTM 640        // [wi 0..80 | pad | h 88..599 | pad], mult of 64
#define H_OFF 88
#define NLSTM 2048

// GEMM tiling (fp16 mma.m16n8k16)
#define BM 128
#define BN 128
#define BK 64
#define ASTH 72                          // smem row stride in halves (144B): ldmatrix conflict-free
#define STGH (128 * ASTH)                // halves per stage sub-buffer = 9216
#define NS 3
#define DSMEM_BYTES (NS * 2 * STGH * 2)  // 110592
#define SST 72                           // fp32 staging row stride (epilogue)

// ---------------- helpers ----------------
__device__ __forceinline__ uint32_t smem_u32(const void* p) {
    uint32_t a;
    asm("{ .reg .u64 t; cvta.to.shared.u64 t, %1; cvt.u32.u64 %0, t; }" : "=r"(a) : "l"(p));
    return a;
}
#define CP_ASYNC16(dst, src) \
    asm volatile("cp.async.cg.shared.global [%0], [%1], 16;" :: "r"(dst), "l"(src))
#define CP_COMMIT() asm volatile("cp.async.commit_group;" ::: "memory")
#define CP_WAIT1()  asm volatile("cp.async.wait_group 1;" ::: "memory")
#define CP_WAIT0()  asm volatile("cp.async.wait_group 0;" ::: "memory")

#define LDMATRIX_X4(r0, r1, r2, r3, addr) \
    asm volatile("ldmatrix.sync.aligned.m8n8.x4.shared.b16 {%0,%1,%2,%3}, [%4];" \
        : "=r"(r0), "=r"(r1), "=r"(r2), "=r"(r3) : "r"(addr))

__device__ __forceinline__ void mma_fp16(float c[4], const uint32_t a[4],
                                         uint32_t b0, uint32_t b1) {
    asm volatile(
        "mma.sync.aligned.m16n8k16.row.col.f32.f16.f16.f32 "
        "{%0,%1,%2,%3}, {%4,%5,%6,%7}, {%8,%9}, {%0,%1,%2,%3};"
        : "+f"(c[0]), "+f"(c[1]), "+f"(c[2]), "+f"(c[3])
        : "r"(a[0]), "r"(a[1]), "r"(a[2]), "r"(a[3]), "r"(b0), "r"(b1));
}

// explicit MUFU-based transcendentals
__device__ __forceinline__ float ex2f_(float x) {
    float y; asm("ex2.approx.f32 %0, %1;" : "=f"(y) : "f"(x)); return y;
}
__device__ __forceinline__ float rcpf_(float x) {
    float y; asm("rcp.approx.f32 %0, %1;" : "=f"(y) : "f"(x)); return y;
}
#define LOG2E_ 1.4426950408889634f
__device__ __forceinline__ float sigf_(float x) {
    return rcpf_(1.f + ex2f_(-LOG2E_ * x));
}
__device__ __forceinline__ float tanhf_(float x) {
    return 2.f * rcpf_(1.f + ex2f_(-2.f * LOG2E_ * x)) - 1.f;
}

// ---------------- device scratch ----------------
__device__ __align__(16) __half g_Apad  [(size_t)BB * KCONV];
__device__ __align__(16) __half g_WeffT [(size_t)NCONV * KCONV];
__device__ float  g_Cconv [(size_t)BB * NCONV];   // stores tanh(conv + bias)
__device__ __align__(16) float g_biasn [NCONV];
__device__ float  g_xstat [(size_t)BB * FPAD];
__device__ float  g_WxT   [(size_t)FPAD * NPAD_LX];
__device__ float  g_Lx    [(size_t)BB * NPAD_LX];
__device__ float  g_rWx   [NPAD_LX];
__device__ float  g_ystat [(size_t)BB * INPC];
__device__ __align__(16) __half g_WcombT[(size_t)NLSTM * KLSTM];
__device__ float  g_bcomb [NLSTM];
__device__ __align__(16) __half g_Acomb [2][(size_t)BB * KLSTM];
__device__ float  g_cbuf  [(size_t)BB * HH];

// ---------------- prep kernels ----------------
__global__ void k_zero_state() {
    int idx = blockIdx.x * blockDim.x + threadIdx.x;
    if (idx < BB * KLSTM / 2) {
        ((uint32_t*)&g_Acomb[0][0])[idx] = 0u;
        ((uint32_t*)&g_Acomb[1][0])[idx] = 0u;
    }
    if (idx < BB * HH)   g_cbuf[idx]  = 0.f;
    if (idx < BB * FPAD) g_xstat[idx] = 0.f;
}
__global__ void k_pad_input(const float* __restrict__ in) {
    int idx = blockIdx.x * blockDim.x + threadIdx.x;
    if (idx >= BB * KCONV) return;
    int b = idx / KCONV, k = idx - b * KCONV;
    g_Apad[idx] = (k < 729) ? __float2half(in[(size_t)b * 729 + k]) : __half(0.f);
}
__global__ void k_build_wefft(const float* __restrict__ w3, const float* __restrict__ w5,
                              const float* __restrict__ w7, const float* __restrict__ w11,
                              const float* __restrict__ w13) {
    int idx = blockIdx.x * blockDim.x + threadIdx.x;
    if (idx >= NCONV * KCONV) return;
    int n = idx / KCONV, k = idx - n * KCONV;
    float v = 0.f;
    if (k < 729 && n < 3645) {
        int s = k / 81, i = k - s * 81;
        int f = n / 9, t = n - f * 9;
        int kidx = f / 81, o = f - kidx * 81;
        const int ksz[5] = {3, 5, 7, 11, 13};
        const float* wp = (kidx == 0) ? w3 : (kidx == 1) ? w5 : (kidx == 2) ? w7
                         : (kidx == 3) ? w11 : w13;
        int kw = ksz[kidx];
        int j = s - t + ((kw - 1) >> 1);
        if (j >= 0 && j < kw) v = wp[(o * 81 + i) * kw + j];
    }
    g_WeffT[idx] = __float2half(v);
}
__global__ void k_build_biasn(const float* __restrict__ b3, const float* __restrict__ b5,
                              const float* __restrict__ b7, const float* __restrict__ b11,
                              const float* __restrict__ b13) {
    int n = blockIdx.x * blockDim.x + threadIdx.x;
    if (n >= NCONV) return;
    float v = 0.f;
    if (n < 3645) {
        int f = n / 9;
        int kidx = f / 81, o = f - kidx * 81;
        v = (kidx == 0) ? b3[o] : (kidx == 1) ? b5[o] : (kidx == 2) ? b7[o]
           : (kidx == 3) ? b11[o] : b13[o];
    }
    g_biasn[n] = v;
}
__global__ void k_build_wxt(const float* __restrict__ regrW) {
    int idx = blockIdx.x * blockDim.x + threadIdx.x;
    if (idx >= FPAD * NPAD_LX) return;
    int f = idx / NPAD_LX, o = idx - f * NPAD_LX;
    g_WxT[idx] = (f < 405 && o < 81) ? regrW[o * 486 + f] : 0.f;
}
__global__ void k_build_wcombt(const float* __restrict__ Wih, const float* __restrict__ Whh,
                               const float* __restrict__ bih, const float* __restrict__ bhh) {
    int idx = blockIdx.x * blockDim.x + threadIdx.x;
    if (idx >= NLSTM * KLSTM) return;
    int n = idx / KLSTM, k = idx - n * KLSTM;
    int g = n & 3, j = n >> 2;
    int r = g * HH + j;
    float v = 0.f;
    if (k < 81)                            v = Wih[(size_t)r * 81 + k];
    else if (k >= H_OFF && k < H_OFF + HH) v = Whh[(size_t)r * HH + (k - H_OFF)];
    g_WcombT[idx] = __float2half(v);
    if (k == 0) g_bcomb[n] = bih[r] + bhh[r];
}
__global__ void k_ystat(const float* __restrict__ in, const float* __restrict__ cosw,
                        const float* __restrict__ cosb) {
    int idx = blockIdx.x * blockDim.x + threadIdx.x;
    if (idx >= BB * INPC) return;
    int b = idx / INPC, i = idx - b * INPC;
    float a = cosb[0];
#pragma unroll
    for (int s = 0; s < TT; s++) a += in[(size_t)b * 729 + s * 81 + i] * cosw[1024 + s];
    g_ystat[idx] = a;
}
__global__ void k_rwx(const float* __restrict__ regrW) {
    int o = threadIdx.x;
    if (o >= NPAD_LX) return;
    float a = 0.f;
    if (o < 81)
        for (int f = 0; f < 405; f++) a += regrW[o * 486 + f];
    g_rWx[o] = a;
}
// Cconv already holds tanh(conv+bias); only the 9-tap weighted sum remains.
__global__ void k_reduce_x(const float* __restrict__ aconvw, const float* __restrict__ aconvb) {
    int idx = blockIdx.x * blockDim.x + threadIdx.x;
    if (idx >= BB * 405) return;
    int b = idx / 405, f = idx - b * 405;
    const float* crow = &g_Cconv[(size_t)b * NCONV + f * 9];
    float acc = aconvb[0];
#pragma unroll
    for (int t = 0; t < TT; t++) acc += crow[t] * aconvw[1024 + t];
    g_xstat[(size_t)b * FPAD + f] = acc;
}

// ---------------- small fp32 GEMM (Lx only) ----------------
__device__ __forceinline__ void gemm_tile(const float* __restrict__ A,
                                          const float* __restrict__ B,
                                          int N, int K, float acc[8][8]) {
    __shared__ float As[8][128];
    __shared__ float Bs[8][128];
    const int tid = threadIdx.x;
    const int bm = blockIdx.y * 128, bn = blockIdx.x * 128;
    const int aRow = tid >> 1, aCol = (tid & 1) << 2;
    const int bRow = tid >> 5, bCol = (tid & 31) << 2;
    const int tx = tid & 15, ty = tid >> 4;
    const float* Ap = A + (size_t)(bm + aRow) * K + aCol;
    const float* Bp = B + (size_t)bRow * N + bn + bCol;
    for (int k0 = 0; k0 < K; k0 += 8) {
        float4 av = *(const float4*)(Ap + k0);
        float4 bv = *(const float4*)(Bp + (size_t)k0 * N);
        As[aCol + 0][aRow] = av.x; As[aCol + 1][aRow] = av.y;
        As[aCol + 2][aRow] = av.z; As[aCol + 3][aRow] = av.w;
        *(float4*)&Bs[bRow][bCol] = bv;
        __syncthreads();
#pragma unroll
        for (int kk = 0; kk < 8; kk++) {
            float a[8], b[8];
            *(float4*)&a[0] = *(const float4*)&As[kk][ty << 2];
            *(float4*)&a[4] = *(const float4*)&As[kk][(ty << 2) + 64];
            *(float4*)&b[0] = *(const float4*)&Bs[kk][tx << 2];
            *(float4*)&b[4] = *(const float4*)&Bs[kk][(tx << 2) + 64];
#pragma unroll
            for (int im = 0; im < 8; im++)
#pragma unroll
                for (int in = 0; in < 8; in++)
                    acc[im][in] += a[im] * b[in];
        }
        __syncthreads();
    }
}
__global__ __launch_bounds__(256) void k_sgemm_lx() {
    float acc[8][8];
#pragma unroll
    for (int i = 0; i < 8; i++)
#pragma unroll
        for (int j = 0; j < 8; j++) acc[i][j] = 0.f;
    gemm_tile(g_xstat, g_WxT, NPAD_LX, FPAD, acc);
    const int tid = threadIdx.x;
    const int tx = tid & 15, ty = tid >> 4;
    const int bm = blockIdx.y * 128, bn = blockIdx.x * 128;
#pragma unroll
    for (int hm = 0; hm < 2; hm++)
#pragma unroll
        for (int i = 0; i < 4; i++) {
            int m = bm + (ty << 2) + hm * 64 + i;
            float4 v0 = make_float4(acc[hm*4+i][0], acc[hm*4+i][1], acc[hm*4+i][2], acc[hm*4+i][3]);
            float4 v1 = make_float4(acc[hm*4+i][4], acc[hm*4+i][5], acc[hm*4+i][6], acc[hm*4+i][7]);
            *(float4*)&g_Lx[(size_t)m * NPAD_LX + bn + (tx << 2)]      = v0;
            *(float4*)&g_Lx[(size_t)m * NPAD_LX + bn + 64 + (tx << 2)] = v1;
        }
}

// ---------------- fp16 mma GEMM engine (BK=64, frag double-buffer) ----------------
template <int KEL>
__device__ __forceinline__ void ld_stage(const __half* __restrict__ Ab,
                                         const __half* __restrict__ Bb,
                                         __half* As, __half* Bs, int kb, int tid) {
    const __half* ag = Ab + kb * BK;
    const __half* bg = Bb + kb * BK;
#pragma unroll
    for (int it = 0; it < 4; it++) {
        int chunk = tid + it * 256;          // 1024 chunks = 128 rows x 8 x 16B
        int r = chunk >> 3, ch = chunk & 7;
        CP_ASYNC16(smem_u32(As + r * ASTH + ch * 8), ag + (size_t)r * KEL + ch * 8);
    }
#pragma unroll
    for (int it = 0; it < 4; it++) {
        int chunk = tid + it * 256;
        int r = chunk >> 3, ch = chunk & 7;
        CP_ASYNC16(smem_u32(Bs + r * ASTH + ch * 8), bg + (size_t)r * KEL + ch * 8);
    }
}

// load A (4x ldmatrix.x4) + B (2x ldmatrix.x4) fragments for one 16-k slice
__device__ __forceinline__ void ld_frags(const __half* As, const __half* Bs, int ks,
                                         int ra, int ca, int rb, int cb,
                                         uint32_t af[4][4], uint32_t bf[8]) {
#pragma unroll
    for (int mt = 0; mt < 4; mt++) {
        uint32_t addr = smem_u32(&As[(ra + mt * 16) * ASTH + ks * 16 + ca]);
        LDMATRIX_X4(af[mt][0], af[mt][1], af[mt][2], af[mt][3], addr);
    }
#pragma unroll
    for (int ntp = 0; ntp < 2; ntp++) {
        uint32_t addr = smem_u32(&Bs[(rb + ntp * 16) * ASTH + ks * 16 + cb]);
        LDMATRIX_X4(bf[4 * ntp + 0], bf[4 * ntp + 1], bf[4 * ntp + 2], bf[4 * ntp + 3], addr);
    }
}

template <int KEL, int KB>
__device__ __forceinline__ void mma_mainloop(const __half* __restrict__ Ab,
                                             const __half* __restrict__ Bb,
                                             float acc[4][4][4], __half* sm) {
    const int tid = threadIdx.x;
    const int warp = tid >> 5, lane = tid & 31;
    const int wm = warp & 1, wn = warp >> 1;

    ld_stage<KEL>(Ab, Bb, sm,            sm + STGH,     0, tid);
    CP_COMMIT();
    ld_stage<KEL>(Ab, Bb, sm + 2 * STGH, sm + 3 * STGH, 1, tid);
    CP_COMMIT();

    const int ra  = wm * 64 + (lane & 15);
    const int ca  = (lane >> 4) << 3;
    const int rb  = wn * 32 + (lane & 7) + ((lane >> 4) << 3);
    const int cb  = ((lane >> 3) & 1) << 3;

    uint32_t af[2][4][4], bf[2][8];

    for (int kb = 0; kb < KB; kb++) {
        if (kb < KB - 1) { CP_WAIT1(); } else { CP_WAIT0(); }
        __syncthreads();
        if (kb + 2 < KB) {
            __half* dst = sm + ((kb + 2) % NS) * 2 * STGH;
            ld_stage<KEL>(Ab, Bb, dst, dst + STGH, kb + 2, tid);
            CP_COMMIT();
        }
        const __half* As = sm + (kb % NS) * 2 * STGH;
        const __half* Bs = As + STGH;

        ld_frags(As, Bs, 0, ra, ca, rb, cb, af[0], bf[0]);
#pragma unroll
        for (int ks = 0; ks < 4; ks++) {
            const int cur = ks & 1;
            if (ks < 3)
                ld_frags(As, Bs, ks + 1, ra, ca, rb, cb, af[cur ^ 1], bf[cur ^ 1]);
#pragma unroll
            for (int mt = 0; mt < 4; mt++)
                mma_fp16(acc[mt][0], af[cur][mt], bf[cur][0], bf[cur][1]);
#pragma unroll
            for (int mt = 0; mt < 4; mt++)
                mma_fp16(acc[mt][1], af[cur][mt], bf[cur][2], bf[cur][3]);
#pragma unroll
            for (int mt = 0; mt < 4; mt++)
                mma_fp16(acc[mt][2], af[cur][mt], bf[cur][4], bf[cur][5]);
#pragma unroll
            for (int mt = 0; mt < 4; mt++)
                mma_fp16(acc[mt][3], af[cur][mt], bf[cur][6], bf[cur][7]);
        }
        __syncthreads();
    }
}

// stage pass-p C columns (nt = 2p, 2p+1) into fp32 smem [128][SST]
__device__ __forceinline__ void stage_pass(float* sf, const float acc[4][4][4],
                                           int p, int lane, int wm, int wn) {
#pragma unroll
    for (int mt = 0; mt < 4; mt++)
#pragma unroll
        for (int ntl = 0; ntl < 2; ntl++) {
            int nt = 2 * p + ntl;
            int r = wm * 64 + mt * 16 + (lane >> 2);
            int cl = wn * 16 + ntl * 8 + 2 * (lane & 3);
            *(float2*)&sf[r * SST + cl]       = make_float2(acc[mt][nt][0], acc[mt][nt][1]);
            *(float2*)&sf[(r + 8) * SST + cl] = make_float2(acc[mt][nt][2], acc[mt][nt][3]);
        }
}

// ---------------- conv GEMM + fused bias/tanh epilogue ----------------
__global__ __launch_bounds__(256, 2) void k_mma_conv() {
    extern __shared__ __half sm[];
    const int tid = threadIdx.x;
    const int lane = tid & 31, warp = tid >> 5;
    const int wm = warp & 1, wn = warp >> 1;
    const int bm = blockIdx.y * BM, bn = blockIdx.x * BN;
    float acc[4][4][4];
#pragma unroll
    for (int i = 0; i < 4; i++)
#pragma unroll
        for (int j = 0; j < 4; j++)
#pragma unroll
            for (int q = 0; q < 4; q++) acc[i][j][q] = 0.f;
    mma_mainloop<KCONV, KCONV / BK>(g_Apad + (size_t)bm * KCONV,
                                    g_WeffT + (size_t)bn * KCONV, acc, sm);

    float* sf = (float*)sm;
    const int row = tid >> 1, m = bm + row;
#pragma unroll
    for (int p = 0; p < 2; p++) {
        if (p) __syncthreads();
        stage_pass(sf, acc, p, lane, wm, wn);
        __syncthreads();
#pragma unroll
        for (int g = 0; g < 2; g++) {
            int wnp = (tid & 1) * 2 + g;
            int cg0 = bn + wnp * 32 + p * 16;
            int cl0 = wnp * 16;
#pragma unroll
            for (int q4 = 0; q4 < 4; q4++) {
                float4 v = *(const float4*)&sf[row * SST + cl0 + 4 * q4];
                float4 bi = *(const float4*)&g_biasn[cg0 + 4 * q4];
                v.x = tanhf_(v.x + bi.x); v.y = tanhf_(v.y + bi.y);
                v.z = tanhf_(v.z + bi.z); v.w = tanhf_(v.w + bi.w);
                *(float4*)&g_Cconv[(size_t)m * NCONV + cg0 + 4 * q4] = v;
            }
        }
    }
}

// ---------------- LSTM GEMM + fused gate epilogue (smem-staged) ----------------
__global__ __launch_bounds__(256, 2) void k_mma_lstm(float* __restrict__ out_enc, int t,
                                                     int bin, int bout) {
    extern __shared__ __half sm[];
    const int tid = threadIdx.x;
    const int lane = tid & 31, warp = tid >> 5;
    const int wm = warp & 1, wn = warp >> 1;
    const int bm = blockIdx.y * BM, bn = blockIdx.x * BN;
    float acc[4][4][4];
#pragma unroll
    for (int i = 0; i < 4; i++)
#pragma unroll
        for (int j = 0; j < 4; j++)
#pragma unroll
            for (int q = 0; q < 4; q++) acc[i][j][q] = 0.f;
    mma_mainloop<KLSTM, KLSTM / BK>(g_Acomb[bin] + (size_t)bm * KLSTM,
                                    g_WcombT + (size_t)bn * KLSTM, acc, sm);

    __half* Aout = g_Acomb[bout];
    float* sf = (float*)sm;
    const int row = tid >> 1, m = bm + row;
#pragma unroll
    for (int p = 0; p < 2; p++) {
        if (p) __syncthreads();
        stage_pass(sf, acc, p, lane, wm, wn);
        __syncthreads();
#pragma unroll
        for (int g = 0; g < 2; g++) {
            int wnp = (tid & 1) * 2 + g;
            int cg0 = bn + wnp * 32 + p * 16;
            int cl0 = wnp * 16;
            int u0 = cg0 >> 2;
            float gv[16], bb[16];
#pragma unroll
            for (int q4 = 0; q4 < 4; q4++) {
                *(float4*)&gv[4 * q4] = *(const float4*)&sf[row * SST + cl0 + 4 * q4];
                *(float4*)&bb[4 * q4] = *(const float4*)&g_bcomb[cg0 + 4 * q4];
            }
            float cold[4];
            *(float4*)&cold[0] = *(const float4*)&g_cbuf[(size_t)m * HH + u0];
            float c4[4], h4[4];
            __half hh[4];
#pragma unroll
            for (int q = 0; q < 4; q++) {
                float iv = sigf_(gv[4 * q + 0] + bb[4 * q + 0]);
                float fv = sigf_(gv[4 * q + 1] + bb[4 * q + 1]);
                float gg = tanhf_(gv[4 * q + 2] + bb[4 * q + 2]);
                float ov = sigf_(gv[4 * q + 3] + bb[4 * q + 3]);
                float c2 = fv * cold[q] + iv * gg;
                c4[q] = c2;
                h4[q] = ov * tanhf_(c2);
                hh[q] = __float2half(h4[q]);
            }
            *(float4*)&g_cbuf[(size_t)m * HH + u0] = *(float4*)&c4[0];
            *(float4*)&out_enc[(size_t)m * (TT * HH) + t * HH + u0] = *(float4*)&h4[0];
            *(uint2*)&Aout[(size_t)m * KLSTM + H_OFF + u0] = *(uint2*)&hh[0];
        }
    }
}

// ---------------- per-step attention (warp per batch, 8/block) ----------------
__global__ __launch_bounds__(256) void k_att(const float* __restrict__ input,
                                             const float* __restrict__ regrW,
                                             const float* __restrict__ regrb,
                                             const float* __restrict__ aconvw,
                                             const float* __restrict__ acosw,
                                             int t, int bin,
                                             float* __restrict__ out_w,
                                             const float* __restrict__ out_enc) {
    __shared__ float Wy[81 * 81];
    __shared__ float ysh[8][81];
    const int tid = threadIdx.x;
    for (int idx = tid; idx < 81 * 81; idx += 256) {
        int o = idx / 81, i = idx - o * 81;
        Wy[idx] = regrW[o * 486 + 405 + i];
    }
    __syncthreads();

    const int w = tid >> 5, l = tid & 31;
    const int b = blockIdx.x * 8 + w;
    __half* Ain = g_Acomb[bin];
    const float* hprev = out_enc + (size_t)b * (TT * HH) + (t - 1) * HH;
    const float* c = g_cbuf + (size_t)b * HH;

    float sx = 0.f, sy = 0.f;
    if (t > 0) {
        for (int k = l; k < HH; k += 32) {
            float hv = hprev[k], cv = c[k];
            sx += hv * aconvw[k] + cv * aconvw[512 + k];
            sy += hv * acosw[k] + cv * acosw[512 + k];
        }
#pragma unroll
        for (int off = 16; off; off >>= 1) {
            sx += __shfl_xor_sync(0xffffffffu, sx, off);
            sy += __shfl_xor_sync(0xffffffffu, sy, off);
        }
    }
    for (int i = l; i < 81; i += 32)
        ysh[w][i] = __cosf(g_ystat[(size_t)b * 81 + i] + sy);
    __syncwarp();

    float lgv[3];
#pragma unroll
    for (int q = 0; q < 3; q++) {
        int o = l + q * 32;
        float acc = -1e30f;
        if (o < 81) {
            acc = g_Lx[(size_t)b * NPAD_LX + o] + sx * g_rWx[o] + regrb[o];
            const float* wrow = &Wy[o * 81];
#pragma unroll 9
            for (int i = 0; i < 81; i++) acc += ysh[w][i] * wrow[i];
        }
        lgv[q] = acc;
    }
    float mx = fmaxf(fmaxf(lgv[0], lgv[1]), lgv[2]);
#pragma unroll
    for (int off = 16; off; off >>= 1) mx = fmaxf(mx, __shfl_xor_sync(0xffffffffu, mx, off));
    float e[3], ssum = 0.f;
#pragma unroll
    for (int q = 0; q < 3; q++) {
        e[q] = (l + q * 32 < 81) ? __expf(lgv[q] - mx) : 0.f;
        ssum += e[q];
    }
#pragma unroll
    for (int off = 16; off; off >>= 1) ssum += __shfl_xor_sync(0xffffffffu, ssum, off);
    float inv = 1.f / ssum;
#pragma unroll
    for (int q = 0; q < 3; q++) {
        int o = l + q * 32;
        if (o < 81) {
            float wi = e[q] * inv * input[(size_t)b * 729 + t * 81 + o];
            Ain[(size_t)b * KLSTM + o] = __float2half(wi);
            out_w[(size_t)b * 729 + t * 81 + o] = wi;
        }
    }
}

// ---------------- launch ----------------
extern "C" void kernel_launch(void* const* d_in, const int* in_sizes, int n_in,
                              void* d_out, int out_size) {
    const float* input  = (const float*)d_in[0];
    const float* w3  = (const float*)d_in[1];  const float* b3  = (const float*)d_in[2];
    const float* w5  = (const float*)d_in[3];  const float* b5  = (const float*)d_in[4];
    const float* w7  = (const float*)d_in[5];  const float* b7  = (const float*)d_in[6];
    const float* w11 = (const float*)d_in[7];  const float* b11 = (const float*)d_in[8];
    const float* w13 = (const float*)d_in[9];  const float* b13 = (const float*)d_in[10];
    const float* aconvw = (const float*)d_in[11]; const float* aconvb = (const float*)d_in[12];
    const float* acosw  = (const float*)d_in[13]; const float* acosb  = (const float*)d_in[14];
    const float* regrW  = (const float*)d_in[15]; const float* regrb  = (const float*)d_in[16];
    const float* Wih = (const float*)d_in[17]; const float* Whh = (const float*)d_in[18];
    const float* bih = (const float*)d_in[19]; const float* bhh = (const float*)d_in[20];

    float* out_w   = (float*)d_out;
    float* out_enc = out_w + (size_t)BB * TT * INPC;

    cudaFuncSetAttribute(k_mma_conv, cudaFuncAttributeMaxDynamicSharedMemorySize, DSMEM_BYTES);
    cudaFuncSetAttribute(k_mma_lstm, cudaFuncAttributeMaxDynamicSharedMemorySize, DSMEM_BYTES);

    const int TH = 256;
    k_zero_state<<<(BB * KLSTM + TH - 1) / TH, TH>>>();
    k_pad_input<<<(BB * KCONV + TH - 1) / TH, TH>>>(input);
    k_build_wefft<<<(NCONV * KCONV + TH - 1) / TH, TH>>>(w3, w5, w7, w11, w13);
    k_build_biasn<<<(NCONV + TH - 1) / TH, TH>>>(b3, b5, b7, b11, b13);
    dim3 gconv(NCONV / BN, BB / BM);
    k_mma_conv<<<gconv, 256, DSMEM_BYTES>>>();

    k_build_wxt<<<(FPAD * NPAD_LX + TH - 1) / TH, TH>>>(regrW);
    k_build_wcombt<<<(NLSTM * KLSTM + TH - 1) / TH, TH>>>(Wih, Whh, bih, bhh);
    k_ystat<<<(BB * INPC + TH - 1) / TH, TH>>>(input, acosw, acosb);
    k_rwx<<<1, NPAD_LX>>>(regrW);
    k_reduce_x<<<(BB * 405 + TH - 1) / TH, TH>>>(aconvw, aconvb);
    dim3 glx(NPAD_LX / 128, BB / 128);
    k_sgemm_lx<<<glx, 256>>>();

    dim3 glstm(NLSTM / BN, BB / BM);
    for (int t = 0; t < TT; t++) {
        int bin = t & 1, bout = (t + 1) & 1;
        k_att<<<BB / 8, 256>>>(input, regrW, regrb, aconvw, acosw, t, bin, out_w, out_enc);
        k_mma_lstm<<<glstm, 256, DSMEM_BYTES>>>(out_enc, t, bin, bout);
    }
}